// round 15
// baseline (speedup 1.0000x reference)
#include <cuda_runtime.h>
#include <math.h>

#define FULL 0xFFFFFFFFu

// Problem constants: B=2, N=2048, C=1024, H=16, D=64, TOPK=32
__device__ float g_q[2*16*2048*64];   // [B,H,N,D]  (exact-order fp32)
__device__ float g_k[2*16*2048*64];   // pre-scaled by 1/8 (exact: *2^-3)
__device__ float g_v[2*16*2048*64];
__device__ float g_x[2*2048*1024];    // attention output, [B,N,C]

__device__ __forceinline__ unsigned f2tf(float x) {
    unsigned r;
    asm("cvt.rna.tf32.f32 %0, %1;" : "=r"(r) : "f"(x));
    return r;
}
__device__ __forceinline__ void split2(float x, unsigned& h, unsigned& l) {
    h = f2tf(x);
    l = f2tf(x - __uint_as_float(h));
}
__device__ __forceinline__ void mma_tf32(float c[4], const unsigned a[4], const unsigned b[2]) {
    asm volatile(
        "mma.sync.aligned.m16n8k8.row.col.f32.tf32.tf32.f32 "
        "{%0,%1,%2,%3}, {%4,%5,%6,%7}, {%8,%9}, {%0,%1,%2,%3};\n"
        : "+f"(c[0]), "+f"(c[1]), "+f"(c[2]), "+f"(c[3])
        : "r"(a[0]), "r"(a[1]), "r"(a[2]), "r"(a[3]),
          "r"(b[0]), "r"(b[1]));
}
// zero-register global->shared 16B async copy (LDGSTS)
__device__ __forceinline__ void cp_async16(unsigned dst, const void* src) {
    asm volatile("cp.async.cg.shared.global [%0], [%1], 16;" :: "r"(dst), "l"(src));
}
__device__ __forceinline__ void cp_async_commit() {
    asm volatile("cp.async.commit_group;");
}
__device__ __forceinline__ void cp_async_wait0() {
    asm volatile("cp.async.wait_group 0;" ::: "memory");
}

// ---------------------------------------------------------------------------
// EXACT-ORDER fp32 SGEMM (bit-matches standard SIMT sgemm): each output is a
// single strictly k-ascending FMA chain. Double-buffered smem, register
// prefetch, ONE barrier per k-tile. Scatter to [B,H,Nseq,D].
// M=4096, N=1024, K=1024. CTA 128x128, 256 thr, 8x8 micro-tile, k-tile 8.
// ---------------------------------------------------------------------------
__global__ __launch_bounds__(256, 2)
void gemm_exact_kernel(const float* __restrict__ A, const float* __restrict__ W,
                       const float* __restrict__ bias, float* __restrict__ out,
                       float scale)
{
    __shared__ float sA[2][8][132];
    __shared__ float sB[2][8][132];

    const int t  = threadIdx.x;
    const int tx = t & 15;
    const int ty = t >> 4;
    const int bm = blockIdx.y * 128;
    const int bn = blockIdx.x * 128;

    float c[8][8];
#pragma unroll
    for (int i = 0; i < 8; i++)
#pragma unroll
        for (int j = 0; j < 8; j++) c[i][j] = 0.f;

    const int lrow = t >> 1;              // 0..127
    const int lk   = (t & 1) * 4;         // 0 or 4
    const float* Ag = A + (size_t)(bm + lrow) * 1024 + lk;
    const float* Wg = W + (size_t)(bn + lrow) * 1024 + lk;

    // preload k-tile 0
    {
        float4 av = *(const float4*)(Ag);
        float4 wv = *(const float4*)(Wg);
        sA[0][lk + 0][lrow] = av.x; sA[0][lk + 1][lrow] = av.y;
        sA[0][lk + 2][lrow] = av.z; sA[0][lk + 3][lrow] = av.w;
        sB[0][lk + 0][lrow] = wv.x; sB[0][lk + 1][lrow] = wv.y;
        sB[0][lk + 2][lrow] = wv.z; sB[0][lk + 3][lrow] = wv.w;
    }
    __syncthreads();

    for (int kt = 0; kt < 128; kt++) {
        const int cb = kt & 1;
        float4 av = make_float4(0.f, 0.f, 0.f, 0.f);
        float4 wv = make_float4(0.f, 0.f, 0.f, 0.f);
        if (kt < 127) {                        // prefetch next tile
            av = *(const float4*)(Ag + (kt + 1) * 8);
            wv = *(const float4*)(Wg + (kt + 1) * 8);
        }

#pragma unroll
        for (int kk = 0; kk < 8; kk++) {       // strictly ascending k
            float a[8], b[8];
            *(float4*)(a)     = *(const float4*)&sA[cb][kk][ty * 8];
            *(float4*)(a + 4) = *(const float4*)&sA[cb][kk][ty * 8 + 4];
            *(float4*)(b)     = *(const float4*)&sB[cb][kk][tx * 8];
            *(float4*)(b + 4) = *(const float4*)&sB[cb][kk][tx * 8 + 4];
#pragma unroll
            for (int i = 0; i < 8; i++)
#pragma unroll
                for (int j = 0; j < 8; j++)
                    c[i][j] = fmaf(a[i], b[j], c[i][j]);
        }

        if (kt < 127) {
            const int nb = cb ^ 1;
            sA[nb][lk + 0][lrow] = av.x; sA[nb][lk + 1][lrow] = av.y;
            sA[nb][lk + 2][lrow] = av.z; sA[nb][lk + 3][lrow] = av.w;
            sB[nb][lk + 0][lrow] = wv.x; sB[nb][lk + 1][lrow] = wv.y;
            sB[nb][lk + 2][lrow] = wv.z; sB[nb][lk + 3][lrow] = wv.w;
        }
        __syncthreads();                       // single barrier per tile
    }

#pragma unroll
    for (int i = 0; i < 8; i++)
#pragma unroll
        for (int j = 0; j < 8; j++) {
            const int mg = bm + ty * 8 + i;
            const int ng = bn + tx * 8 + j;
            const float val = (c[i][j] + bias[ng]) * scale;
            const int b = mg >> 11, ns = mg & 2047;
            const int h = ng >> 6,  d  = ng & 63;
            out[(size_t)((b * 16 + h) * 2048 + ns) * 64 + d] = val;
        }
}

// ---------------------------------------------------------------------------
// 2-way-split 3-mma tf32 GEMM (~1e-7 values) for V-proj (MODE 0) and
// out-proj (MODE 1). Value-only paths; accumulation order free.
// ---------------------------------------------------------------------------
template<int MODE>
__global__ __launch_bounds__(256)
void gemm_tf32_kernel(const float* __restrict__ A, const float* __restrict__ W,
                      const float* __restrict__ bias, float* __restrict__ out,
                      float scale)
{
    __shared__ unsigned sAh[128][20], sAl[128][20];
    __shared__ unsigned sBh[128][20], sBl[128][20];

    const int t    = threadIdx.x;
    const int lane = t & 31;
    const int w    = t >> 5;
    const int grp  = lane >> 2;
    const int tg   = lane & 3;
    const int wm   = w & 1;
    const int wn   = w >> 1;
    const int bm   = blockIdx.y * 128;
    const int bn   = blockIdx.x * 128;

    float c[4][4][4];
#pragma unroll
    for (int mt = 0; mt < 4; mt++)
#pragma unroll
        for (int nt = 0; nt < 4; nt++)
#pragma unroll
            for (int e = 0; e < 4; e++) c[mt][nt][e] = 0.f;

    const int lrow = t >> 1;
    const int lcol = (t & 1) * 8;
    const float* Ag = A + (size_t)(bm + lrow) * 1024 + lcol;
    const float* Wg = W + (size_t)(bn + lrow) * 1024 + lcol;

    for (int kt = 0; kt < 64; kt++) {
        float av[8], wv[8];
        *(float4*)(av)     = *(const float4*)(Ag + kt * 16);
        *(float4*)(av + 4) = *(const float4*)(Ag + kt * 16 + 4);
        *(float4*)(wv)     = *(const float4*)(Wg + kt * 16);
        *(float4*)(wv + 4) = *(const float4*)(Wg + kt * 16 + 4);
        __syncthreads();
#pragma unroll
        for (int j = 0; j < 8; j++) {
            unsigned h, l;
            split2(av[j], h, l);
            sAh[lrow][lcol + j] = h; sAl[lrow][lcol + j] = l;
            split2(wv[j], h, l);
            sBh[lrow][lcol + j] = h; sBl[lrow][lcol + j] = l;
        }
        __syncthreads();

#pragma unroll
        for (int ks = 0; ks < 2; ks++) {
            const int kk = ks * 8 + tg;
            unsigned ah[4][4], al[4][4], bh2[4][2], bl2[4][2];
#pragma unroll
            for (int mt = 0; mt < 4; mt++) {
                const int r = wm * 64 + mt * 16 + grp;
                ah[mt][0] = sAh[r][kk];     al[mt][0] = sAl[r][kk];
                ah[mt][1] = sAh[r + 8][kk]; al[mt][1] = sAl[r + 8][kk];
                ah[mt][2] = sAh[r][kk + 4]; al[mt][2] = sAl[r][kk + 4];
                ah[mt][3] = sAh[r + 8][kk + 4]; al[mt][3] = sAl[r + 8][kk + 4];
            }
#pragma unroll
            for (int nt = 0; nt < 4; nt++) {
                const int q = wn * 32 + nt * 8 + grp;
                bh2[nt][0] = sBh[q][kk];     bl2[nt][0] = sBl[q][kk];
                bh2[nt][1] = sBh[q][kk + 4]; bl2[nt][1] = sBl[q][kk + 4];
            }
#pragma unroll
            for (int mt = 0; mt < 4; mt++)
#pragma unroll
                for (int nt = 0; nt < 4; nt++) {
                    mma_tf32(c[mt][nt], ah[mt], bl2[nt]);
                    mma_tf32(c[mt][nt], al[mt], bh2[nt]);
                    mma_tf32(c[mt][nt], ah[mt], bh2[nt]);
                }
        }
    }

#pragma unroll
    for (int mt = 0; mt < 4; mt++)
#pragma unroll
        for (int nt = 0; nt < 4; nt++) {
            const int mg0 = bm + wm * 64 + mt * 16 + grp;
            const int ng0 = bn + wn * 32 + nt * 8 + tg * 2;
#pragma unroll
            for (int e = 0; e < 4; e++) {
                const int mg = mg0 + (e >> 1) * 8;
                const int ng = ng0 + (e & 1);
                const float val = (c[mt][nt][e] + bias[ng]) * scale;
                if (MODE == 0) {
                    const int b = mg >> 11, ns = mg & 2047;
                    const int h = ng >> 6,  d  = ng & 63;
                    out[(size_t)((b * 16 + h) * 2048 + ns) * 64 + d] = val;
                } else {
                    out[(size_t)mg * 1024 + ng] = val;
                }
            }
        }
}

// ---------------------------------------------------------------------------
// Fused attention — 128-row CTA (round-12 work decomposition) with 512
// threads: same per-CTA work and K traffic, DOUBLE the warps for latency
// hiding (32 warps/SM at 2 CTAs/SM).
//  - scores: scalar fp32 FMA, strictly d-ascending chain (selection-critical)
//  - streaming top-32 (exact lax.top_k semantics, selection-critical)
//  - epilogue: order-free butterfly softmax + direct PV accumulation
// Double-buffered K tiles via cp.async, one barrier per tile.
// grid (16, 32), 512 thr = 16 warps; warp owns 8 rows; micro-tile 4x4.
// smem: sQ[128][68] + 2*sK[64][68] + sS[128][68] = 104448 B -> 2 CTAs/SM.
// ---------------------------------------------------------------------------
#define ATTN_SMEM ((128 * 68 + 2 * 64 * 68 + 128 * 68) * 4)

__global__ __launch_bounds__(512, 2)
void attn_topk_kernel(const float* __restrict__ qb, const float* __restrict__ kb,
                      const float* __restrict__ vb, float* __restrict__ xb)
{
    extern __shared__ float smf[];
    float (*sQ)[68]  = (float(*)[68])smf;
    float (*sK0)[68] = (float(*)[68])(smf + 128 * 68);
    float (*sK1)[68] = (float(*)[68])(smf + 128 * 68 + 64 * 68);
    float (*sS)[68]  = (float(*)[68])(smf + 128 * 68 + 2 * 64 * 68);

    const int t    = threadIdx.x;
    const int lane = t & 31;
    const int w    = t >> 5;        // 0..15
    const int tx   = t & 15;
    const int ty   = t >> 4;        // 0..31; warp w has ty in {2w, 2w+1}
    const int bh   = blockIdx.y;
    const int q0   = blockIdx.x * 128;
    const int b    = bh >> 4, h = bh & 15;

    const float* Q  = qb + (size_t)bh * 2048 * 64;
    const float* Kp = kb + (size_t)bh * 2048 * 64;
    const float* Vp = vb + (size_t)bh * 2048 * 64;

    // per-thread K-tile load coords: rows kr, kr+32; cols kc4*4
    const int kr  = t >> 4;         // 0..31
    const int kc4 = t & 15;         // 0..15

    // load Q tile [128][64] and preload K tile 0
    {
#pragma unroll
        for (int i = 0; i < 4; i++) {
            const int row = kr + 32 * i;     // 0..127
            *(float4*)&sQ[row][kc4 * 4] =
                *(const float4*)(Q + (size_t)(q0 + row) * 64 + kc4 * 4);
        }
#pragma unroll
        for (int i = 0; i < 2; i++) {
            const int row = kr + 32 * i;     // 0..63
            *(float4*)&sK0[row][kc4 * 4] =
                *(const float4*)(Kp + (size_t)row * 64 + kc4 * 4);
        }
    }
    __syncthreads();

    // top-32 lists: warp w owns rows w*8..w*8+7; lane holds rank lane (ascending)
    float lv[8]; int li[8];
#pragma unroll
    for (int rr = 0; rr < 8; rr++) { lv[rr] = -INFINITY; li[rr] = 0; }

    for (int kt = 0; kt < 32; kt++) {
        float (*cur)[68] = (kt & 1) ? sK1 : sK0;
        float (*nxt)[68] = (kt & 1) ? sK0 : sK1;

        // zero-register async prefetch of next K tile (overlaps compute+topk)
        if (kt < 31) {
#pragma unroll
            for (int i = 0; i < 2; i++) {
                const int row = kr + 32 * i;
                cp_async16((unsigned)__cvta_generic_to_shared(&nxt[row][kc4 * 4]),
                           Kp + (size_t)((kt + 1) * 64 + row) * 64 + kc4 * 4);
            }
            cp_async_commit();
        }

        // scores: rows ty*4+i (4), keys tx+16*j (4); d-ascending FMA chain
        float c[4][4];
#pragma unroll
        for (int i = 0; i < 4; i++)
#pragma unroll
            for (int j = 0; j < 4; j++) c[i][j] = 0.f;
#pragma unroll
        for (int dg = 0; dg < 16; dg++) {
            float4 a4[4], b4[4];
#pragma unroll
            for (int i = 0; i < 4; i++) a4[i] = *(const float4*)&sQ[ty * 4 + i][dg * 4];
#pragma unroll
            for (int j = 0; j < 4; j++) b4[j] = *(const float4*)&cur[tx + 16 * j][dg * 4];
#pragma unroll
            for (int i = 0; i < 4; i++)
#pragma unroll
                for (int j = 0; j < 4; j++) {
                    c[i][j] = fmaf(a4[i].x, b4[j].x, c[i][j]);
                    c[i][j] = fmaf(a4[i].y, b4[j].y, c[i][j]);
                    c[i][j] = fmaf(a4[i].z, b4[j].z, c[i][j]);
                    c[i][j] = fmaf(a4[i].w, b4[j].w, c[i][j]);
                }
        }
        // sS rows ty*4+i are warp-local (warp w <=> rows 8w..8w+7)
#pragma unroll
        for (int i = 0; i < 4; i++)
#pragma unroll
            for (int j = 0; j < 4; j++)
                sS[ty * 4 + i][tx + 16 * j] = c[i][j];
        __syncwarp();

        // streaming top-32 merge (ascending candidate index; strict > keeps
        // the earlier index on ties, matching lax.top_k)
#pragma unroll
        for (int rr = 0; rr < 8; rr++) {
            const int r = w * 8 + rr;
#pragma unroll
            for (int j = 0; j < 2; j++) {
                const float cand = sS[r][j * 32 + lane];
                const int   ci   = kt * 64 + j * 32 + lane;
                float minv = __shfl_sync(FULL, lv[rr], 0);
                unsigned mk = __ballot_sync(FULL, cand > minv);
                while (mk) {
                    const int src = __ffs(mk) - 1;
                    mk &= mk - 1;
                    const float cv   = __shfl_sync(FULL, cand, src);
                    const int   cidx = __shfl_sync(FULL, ci, src);
                    if (cv > minv) {
                        const unsigned lt  = __ballot_sync(FULL, lv[rr] < cv);
                        const int      pos = __popc(lt);
                        const float nv = __shfl_down_sync(FULL, lv[rr], 1);
                        const int   ni = __shfl_down_sync(FULL, li[rr], 1);
                        if (lane < pos - 1)       { lv[rr] = nv; li[rr] = ni; }
                        else if (lane == pos - 1) { lv[rr] = cv; li[rr] = cidx; }
                        minv = __shfl_sync(FULL, lv[rr], 0);
                    }
                }
            }
        }

        if (kt < 31) cp_async_wait0();   // prefetched tile landed
        __syncthreads();                 // single barrier per tile
    }

    // FAST epilogue (value-only path; order-free): butterfly softmax sum,
    // direct PV accumulation in list order.
#pragma unroll 1
    for (int rr = 0; rr < 8; rr++) {
        const float v  = lv[rr];
        const int   ki = li[rr];
        const float mx = __shfl_sync(FULL, v, 31);   // lane 31 holds the max
        const float e  = expf(v - mx);
        float s = e;
#pragma unroll
        for (int o = 16; o > 0; o >>= 1) s += __shfl_xor_sync(FULL, s, o);
        const float wt = e / s;

        // PV: direct accumulation over the 32 kept (weight, index) pairs
        float acc0 = 0.f, acc1 = 0.f;
#pragma unroll
        for (int s2 = 0; s2 < 32; s2++) {
            const float w2 = __shfl_sync(FULL, wt, s2);
            const int   k2 = __shfl_sync(FULL, ki, s2);
            const float* vr = Vp + (size_t)k2 * 64;
            acc0 = fmaf(w2, vr[lane], acc0);
            acc1 = fmaf(w2, vr[lane + 32], acc1);
        }
        const int qrow = q0 + w * 8 + rr;
        float* xo = xb + (size_t)(b * 2048 + qrow) * 1024 + h * 64;
        xo[lane]      = acc0;
        xo[lane + 32] = acc1;
    }
}

// ---------------------------------------------------------------------------
extern "C" void kernel_launch(void* const* d_in, const int* in_sizes, int n_in,
                              void* d_out, int out_size)
{
    const float* hs = (const float*)d_in[0];
    const float* Wq = (const float*)d_in[1];
    const float* bq = (const float*)d_in[2];
    const float* Wk = (const float*)d_in[3];
    const float* bk = (const float*)d_in[4];
    const float* Wv = (const float*)d_in[5];
    const float* bv = (const float*)d_in[6];
    const float* Wo = (const float*)d_in[7];
    const float* bo = (const float*)d_in[8];
    float* out = (float*)d_out;

    float *qp, *kp, *vp, *xp;
    cudaGetSymbolAddress((void**)&qp, g_q);
    cudaGetSymbolAddress((void**)&kp, g_k);
    cudaGetSymbolAddress((void**)&vp, g_v);
    cudaGetSymbolAddress((void**)&xp, g_x);

    cudaFuncSetAttribute(attn_topk_kernel,
                         cudaFuncAttributeMaxDynamicSharedMemorySize, ATTN_SMEM);

    const dim3 gblk(8, 32);
    gemm_exact_kernel<<<gblk, 256>>>(hs, Wq, bq, qp, 1.0f);     // exact fp32 order
    gemm_exact_kernel<<<gblk, 256>>>(hs, Wk, bk, kp, 0.125f);   // exact; *2^-3 exact
    gemm_tf32_kernel<0><<<gblk, 256>>>(hs, Wv, bv, vp, 1.0f);
    attn_topk_kernel<<<dim3(16, 32), 512, ATTN_SMEM>>>(qp, kp, vp, xp);
    gemm_tf32_kernel<1><<<gblk, 256>>>(xp, Wo, bo, out, 1.0f);
}

// round 16
// speedup vs baseline: 1.1752x; 1.1752x over previous
#include <cuda_runtime.h>
#include <math.h>

#define FULL 0xFFFFFFFFu

// Problem constants: B=2, N=2048, C=1024, H=16, D=64, TOPK=32
__device__ float g_q[2*16*2048*64];   // [B,H,N,D]  (exact-order fp32)
__device__ float g_k[2*16*2048*64];   // pre-scaled by 1/8 (exact: *2^-3)
__device__ float g_v[2*16*2048*64];
__device__ float g_x[2*2048*1024];    // attention output, [B,N,C]

__device__ __forceinline__ unsigned f2tf(float x) {
    unsigned r;
    asm("cvt.rna.tf32.f32 %0, %1;" : "=r"(r) : "f"(x));
    return r;
}
__device__ __forceinline__ void split2(float x, unsigned& h, unsigned& l) {
    h = f2tf(x);
    l = f2tf(x - __uint_as_float(h));
}
__device__ __forceinline__ void mma_tf32(float c[4], const unsigned a[4], const unsigned b[2]) {
    asm volatile(
        "mma.sync.aligned.m16n8k8.row.col.f32.tf32.tf32.f32 "
        "{%0,%1,%2,%3}, {%4,%5,%6,%7}, {%8,%9}, {%0,%1,%2,%3};\n"
        : "+f"(c[0]), "+f"(c[1]), "+f"(c[2]), "+f"(c[3])
        : "r"(a[0]), "r"(a[1]), "r"(a[2]), "r"(a[3]),
          "r"(b[0]), "r"(b[1]));
}
// zero-register global->shared 16B async copy (LDGSTS)
__device__ __forceinline__ void cp_async16(unsigned dst, const void* src) {
    asm volatile("cp.async.cg.shared.global [%0], [%1], 16;" :: "r"(dst), "l"(src));
}
__device__ __forceinline__ void cp_async_commit() {
    asm volatile("cp.async.commit_group;");
}
__device__ __forceinline__ void cp_async_wait0() {
    asm volatile("cp.async.wait_group 0;" ::: "memory");
}

// ---------------------------------------------------------------------------
// EXACT-ORDER fp32 SGEMM (bit-matches standard SIMT sgemm): each output is a
// single strictly k-ascending FMA chain. Double-buffered smem, register
// prefetch, ONE barrier per k-tile. Scatter to [B,H,Nseq,D].
// M=4096, N=1024, K=1024. CTA 128x128, 256 thr, 8x8 micro-tile, k-tile 8.
// ---------------------------------------------------------------------------
__global__ __launch_bounds__(256, 2)
void gemm_exact_kernel(const float* __restrict__ A, const float* __restrict__ W,
                       const float* __restrict__ bias, float* __restrict__ out,
                       float scale)
{
    __shared__ float sA[2][8][132];
    __shared__ float sB[2][8][132];

    const int t  = threadIdx.x;
    const int tx = t & 15;
    const int ty = t >> 4;
    const int bm = blockIdx.y * 128;
    const int bn = blockIdx.x * 128;

    float c[8][8];
#pragma unroll
    for (int i = 0; i < 8; i++)
#pragma unroll
        for (int j = 0; j < 8; j++) c[i][j] = 0.f;

    const int lrow = t >> 1;              // 0..127
    const int lk   = (t & 1) * 4;         // 0 or 4
    const float* Ag = A + (size_t)(bm + lrow) * 1024 + lk;
    const float* Wg = W + (size_t)(bn + lrow) * 1024 + lk;

    // preload k-tile 0
    {
        float4 av = *(const float4*)(Ag);
        float4 wv = *(const float4*)(Wg);
        sA[0][lk + 0][lrow] = av.x; sA[0][lk + 1][lrow] = av.y;
        sA[0][lk + 2][lrow] = av.z; sA[0][lk + 3][lrow] = av.w;
        sB[0][lk + 0][lrow] = wv.x; sB[0][lk + 1][lrow] = wv.y;
        sB[0][lk + 2][lrow] = wv.z; sB[0][lk + 3][lrow] = wv.w;
    }
    __syncthreads();

    for (int kt = 0; kt < 128; kt++) {
        const int cb = kt & 1;
        float4 av = make_float4(0.f, 0.f, 0.f, 0.f);
        float4 wv = make_float4(0.f, 0.f, 0.f, 0.f);
        if (kt < 127) {                        // prefetch next tile
            av = *(const float4*)(Ag + (kt + 1) * 8);
            wv = *(const float4*)(Wg + (kt + 1) * 8);
        }

#pragma unroll
        for (int kk = 0; kk < 8; kk++) {       // strictly ascending k
            float a[8], b[8];
            *(float4*)(a)     = *(const float4*)&sA[cb][kk][ty * 8];
            *(float4*)(a + 4) = *(const float4*)&sA[cb][kk][ty * 8 + 4];
            *(float4*)(b)     = *(const float4*)&sB[cb][kk][tx * 8];
            *(float4*)(b + 4) = *(const float4*)&sB[cb][kk][tx * 8 + 4];
#pragma unroll
            for (int i = 0; i < 8; i++)
#pragma unroll
                for (int j = 0; j < 8; j++)
                    c[i][j] = fmaf(a[i], b[j], c[i][j]);
        }

        if (kt < 127) {
            const int nb = cb ^ 1;
            sA[nb][lk + 0][lrow] = av.x; sA[nb][lk + 1][lrow] = av.y;
            sA[nb][lk + 2][lrow] = av.z; sA[nb][lk + 3][lrow] = av.w;
            sB[nb][lk + 0][lrow] = wv.x; sB[nb][lk + 1][lrow] = wv.y;
            sB[nb][lk + 2][lrow] = wv.z; sB[nb][lk + 3][lrow] = wv.w;
        }
        __syncthreads();                       // single barrier per tile
    }

#pragma unroll
    for (int i = 0; i < 8; i++)
#pragma unroll
        for (int j = 0; j < 8; j++) {
            const int mg = bm + ty * 8 + i;
            const int ng = bn + tx * 8 + j;
            const float val = (c[i][j] + bias[ng]) * scale;
            const int b = mg >> 11, ns = mg & 2047;
            const int h = ng >> 6,  d  = ng & 63;
            out[(size_t)((b * 16 + h) * 2048 + ns) * 64 + d] = val;
        }
}

// ---------------------------------------------------------------------------
// 2-way-split 3-mma tf32 GEMM (~1e-7 values) for V-proj (MODE 0) and
// out-proj (MODE 1). Value-only paths; accumulation order free.
// ---------------------------------------------------------------------------
template<int MODE>
__global__ __launch_bounds__(256)
void gemm_tf32_kernel(const float* __restrict__ A, const float* __restrict__ W,
                      const float* __restrict__ bias, float* __restrict__ out,
                      float scale)
{
    __shared__ unsigned sAh[128][20], sAl[128][20];
    __shared__ unsigned sBh[128][20], sBl[128][20];

    const int t    = threadIdx.x;
    const int lane = t & 31;
    const int w    = t >> 5;
    const int grp  = lane >> 2;
    const int tg   = lane & 3;
    const int wm   = w & 1;
    const int wn   = w >> 1;
    const int bm   = blockIdx.y * 128;
    const int bn   = blockIdx.x * 128;

    float c[4][4][4];
#pragma unroll
    for (int mt = 0; mt < 4; mt++)
#pragma unroll
        for (int nt = 0; nt < 4; nt++)
#pragma unroll
            for (int e = 0; e < 4; e++) c[mt][nt][e] = 0.f;

    const int lrow = t >> 1;
    const int lcol = (t & 1) * 8;
    const float* Ag = A + (size_t)(bm + lrow) * 1024 + lcol;
    const float* Wg = W + (size_t)(bn + lrow) * 1024 + lcol;

    for (int kt = 0; kt < 64; kt++) {
        float av[8], wv[8];
        *(float4*)(av)     = *(const float4*)(Ag + kt * 16);
        *(float4*)(av + 4) = *(const float4*)(Ag + kt * 16 + 4);
        *(float4*)(wv)     = *(const float4*)(Wg + kt * 16);
        *(float4*)(wv + 4) = *(const float4*)(Wg + kt * 16 + 4);
        __syncthreads();
#pragma unroll
        for (int j = 0; j < 8; j++) {
            unsigned h, l;
            split2(av[j], h, l);
            sAh[lrow][lcol + j] = h; sAl[lrow][lcol + j] = l;
            split2(wv[j], h, l);
            sBh[lrow][lcol + j] = h; sBl[lrow][lcol + j] = l;
        }
        __syncthreads();

#pragma unroll
        for (int ks = 0; ks < 2; ks++) {
            const int kk = ks * 8 + tg;
            unsigned ah[4][4], al[4][4], bh2[4][2], bl2[4][2];
#pragma unroll
            for (int mt = 0; mt < 4; mt++) {
                const int r = wm * 64 + mt * 16 + grp;
                ah[mt][0] = sAh[r][kk];     al[mt][0] = sAl[r][kk];
                ah[mt][1] = sAh[r + 8][kk]; al[mt][1] = sAl[r + 8][kk];
                ah[mt][2] = sAh[r][kk + 4]; al[mt][2] = sAl[r][kk + 4];
                ah[mt][3] = sAh[r + 8][kk + 4]; al[mt][3] = sAl[r + 8][kk + 4];
            }
#pragma unroll
            for (int nt = 0; nt < 4; nt++) {
                const int q = wn * 32 + nt * 8 + grp;
                bh2[nt][0] = sBh[q][kk];     bl2[nt][0] = sBl[q][kk];
                bh2[nt][1] = sBh[q][kk + 4]; bl2[nt][1] = sBl[q][kk + 4];
            }
#pragma unroll
            for (int mt = 0; mt < 4; mt++)
#pragma unroll
                for (int nt = 0; nt < 4; nt++) {
                    mma_tf32(c[mt][nt], ah[mt], bl2[nt]);
                    mma_tf32(c[mt][nt], al[mt], bh2[nt]);
                    mma_tf32(c[mt][nt], ah[mt], bh2[nt]);
                }
        }
    }

#pragma unroll
    for (int mt = 0; mt < 4; mt++)
#pragma unroll
        for (int nt = 0; nt < 4; nt++) {
            const int mg0 = bm + wm * 64 + mt * 16 + grp;
            const int ng0 = bn + wn * 32 + nt * 8 + tg * 2;
#pragma unroll
            for (int e = 0; e < 4; e++) {
                const int mg = mg0 + (e >> 1) * 8;
                const int ng = ng0 + (e & 1);
                const float val = (c[mt][nt][e] + bias[ng]) * scale;
                if (MODE == 0) {
                    const int b = mg >> 11, ns = mg & 2047;
                    const int h = ng >> 6,  d  = ng & 63;
                    out[(size_t)((b * 16 + h) * 2048 + ns) * 64 + d] = val;
                } else {
                    out[(size_t)mg * 1024 + ng] = val;
                }
            }
        }
}

// ---------------------------------------------------------------------------
// Fused attention (round-12 champion decomposition):
//  - scores: scalar fp32 FMA, strictly d-ascending chain (selection-critical)
//  - streaming top-32 (exact lax.top_k semantics, selection-critical)
//    MERGE OPT: candidate index derived by ALU (kt*64+j*32+src) instead of a
//    shfl — bit-identical, one fewer MIO op per insertion.
//  - epilogue: order-free butterfly softmax + direct PV accumulation
// Double-buffered K tiles via cp.async, one barrier per tile, 2 CTAs/SM.
// CTA = 128 q-rows, 64-key tiles. grid (16, 32), 256 thr = 8 warps.
// smem: sQ[128][68] + 2*sK[64][68] + sS[128][68] = 104448 B.
// ---------------------------------------------------------------------------
#define ATTN_SMEM ((128 * 68 + 2 * 64 * 68 + 128 * 68) * 4)

__global__ __launch_bounds__(256, 2)
void attn_topk_kernel(const float* __restrict__ qb, const float* __restrict__ kb,
                      const float* __restrict__ vb, float* __restrict__ xb)
{
    extern __shared__ float smf[];
    float (*sQ)[68]  = (float(*)[68])smf;
    float (*sK0)[68] = (float(*)[68])(smf + 128 * 68);
    float (*sK1)[68] = (float(*)[68])(smf + 128 * 68 + 64 * 68);
    float (*sS)[68]  = (float(*)[68])(smf + 128 * 68 + 2 * 64 * 68);

    const int t    = threadIdx.x;
    const int lane = t & 31;
    const int w    = t >> 5;
    const int tx   = t & 15;
    const int ty   = t >> 4;
    const int bh   = blockIdx.y;
    const int q0   = blockIdx.x * 128;
    const int b    = bh >> 4, h = bh & 15;

    const float* Q  = qb + (size_t)bh * 2048 * 64;
    const float* Kp = kb + (size_t)bh * 2048 * 64;
    const float* Vp = vb + (size_t)bh * 2048 * 64;

    // per-thread K-tile load coords: rows krow+16i, cols kc4*4
    const int krow = t >> 4;        // 0..15
    const int kc4  = t & 15;        // 0..15

    // load Q tile [128][64] and preload K tile 0
    {
#pragma unroll
        for (int i = 0; i < 8; i++) {
            const int fi  = t + 256 * i;
            const int row = fi >> 4, c4 = fi & 15;
            *(float4*)&sQ[row][c4 * 4] =
                *(const float4*)(Q + (size_t)(q0 + row) * 64 + c4 * 4);
        }
#pragma unroll
        for (int i = 0; i < 4; i++) {
            const int row = krow + 16 * i;
            *(float4*)&sK0[row][kc4 * 4] =
                *(const float4*)(Kp + (size_t)row * 64 + kc4 * 4);
        }
    }
    __syncthreads();

    // top-32 lists: warp w owns rows w*16..w*16+15; lane holds rank lane (ascending)
    float lv[16]; int li[16];
#pragma unroll
    for (int rr = 0; rr < 16; rr++) { lv[rr] = -INFINITY; li[rr] = 0; }

    for (int kt = 0; kt < 32; kt++) {
        float (*cur)[68] = (kt & 1) ? sK1 : sK0;
        float (*nxt)[68] = (kt & 1) ? sK0 : sK1;

        // zero-register async prefetch of next K tile (overlaps compute+topk)
        if (kt < 31) {
#pragma unroll
            for (int i = 0; i < 4; i++) {
                const int row = krow + 16 * i;
                cp_async16((unsigned)__cvta_generic_to_shared(&nxt[row][kc4 * 4]),
                           Kp + (size_t)((kt + 1) * 64 + row) * 64 + kc4 * 4);
            }
            cp_async_commit();
        }

        // scores: rows ty*8+i (8), keys tx+16*j (4); d-ascending FMA chain
        float c[8][4];
#pragma unroll
        for (int i = 0; i < 8; i++)
#pragma unroll
            for (int j = 0; j < 4; j++) c[i][j] = 0.f;
#pragma unroll
        for (int dg = 0; dg < 16; dg++) {
            float4 a4[8], b4[4];
#pragma unroll
            for (int i = 0; i < 8; i++) a4[i] = *(const float4*)&sQ[ty * 8 + i][dg * 4];
#pragma unroll
            for (int j = 0; j < 4; j++) b4[j] = *(const float4*)&cur[tx + 16 * j][dg * 4];
#pragma unroll
            for (int i = 0; i < 8; i++)
#pragma unroll
                for (int j = 0; j < 4; j++) {
                    c[i][j] = fmaf(a4[i].x, b4[j].x, c[i][j]);
                    c[i][j] = fmaf(a4[i].y, b4[j].y, c[i][j]);
                    c[i][j] = fmaf(a4[i].z, b4[j].z, c[i][j]);
                    c[i][j] = fmaf(a4[i].w, b4[j].w, c[i][j]);
                }
        }
        // sS rows ty*8+i are warp-local (warp w <=> rows 16w..16w+15)
#pragma unroll
        for (int i = 0; i < 8; i++)
#pragma unroll
            for (int j = 0; j < 4; j++)
                sS[ty * 8 + i][tx + 16 * j] = c[i][j];
        __syncwarp();

        // streaming top-32 merge (ascending candidate index; strict > keeps
        // the earlier index on ties, matching lax.top_k).
        // Candidate index is computed by ALU from the source lane — no shfl.
#pragma unroll
        for (int rr = 0; rr < 16; rr++) {
            const int r = w * 16 + rr;
#pragma unroll
            for (int j = 0; j < 2; j++) {
                const float cand = sS[r][j * 32 + lane];
                const int   base = kt * 64 + j * 32;
                float minv = __shfl_sync(FULL, lv[rr], 0);
                unsigned mk = __ballot_sync(FULL, cand > minv);
                while (mk) {
                    const int src = __ffs(mk) - 1;
                    mk &= mk - 1;
                    const float cv   = __shfl_sync(FULL, cand, src);
                    const int   cidx = base + src;      // ALU, not shfl
                    if (cv > minv) {
                        const unsigned lt  = __ballot_sync(FULL, lv[rr] < cv);
                        const int      pos = __popc(lt);
                        const float nv = __shfl_down_sync(FULL, lv[rr], 1);
                        const int   ni = __shfl_down_sync(FULL, li[rr], 1);
                        if (lane < pos - 1)       { lv[rr] = nv; li[rr] = ni; }
                        else if (lane == pos - 1) { lv[rr] = cv; li[rr] = cidx; }
                        minv = __shfl_sync(FULL, lv[rr], 0);
                    }
                }
            }
        }

        if (kt < 31) cp_async_wait0();   // prefetched tile landed
        __syncthreads();                 // single barrier per tile
    }

    // FAST epilogue (value-only path; order-free): butterfly softmax sum,
    // direct PV accumulation in list order.
#pragma unroll 1
    for (int rr = 0; rr < 16; rr++) {
        const float v  = lv[rr];
        const int   ki = li[rr];
        const float mx = __shfl_sync(FULL, v, 31);   // lane 31 holds the max
        const float e  = expf(v - mx);
        float s = e;
#pragma unroll
        for (int o = 16; o > 0; o >>= 1) s += __shfl_xor_sync(FULL, s, o);
        const float wt = e / s;

        // PV: direct accumulation over the 32 kept (weight, index) pairs
        float acc0 = 0.f, acc1 = 0.f;
#pragma unroll
        for (int s2 = 0; s2 < 32; s2++) {
            const float w2 = __shfl_sync(FULL, wt, s2);
            const int   k2 = __shfl_sync(FULL, ki, s2);
            const float* vr = Vp + (size_t)k2 * 64;
            acc0 = fmaf(w2, vr[lane], acc0);
            acc1 = fmaf(w2, vr[lane + 32], acc1);
        }
        const int qrow = q0 + w * 16 + rr;
        float* xo = xb + (size_t)(b * 2048 + qrow) * 1024 + h * 64;
        xo[lane]      = acc0;
        xo[lane + 32] = acc1;
    }
}

// ---------------------------------------------------------------------------
extern "C" void kernel_launch(void* const* d_in, const int* in_sizes, int n_in,
                              void* d_out, int out_size)
{
    const float* hs = (const float*)d_in[0];
    const float* Wq = (const float*)d_in[1];
    const float* bq = (const float*)d_in[2];
    const float* Wk = (const float*)d_in[3];
    const float* bk = (const float*)d_in[4];
    const float* Wv = (const float*)d_in[5];
    const float* bv = (const float*)d_in[6];
    const float* Wo = (const float*)d_in[7];
    const float* bo = (const float*)d_in[8];
    float* out = (float*)d_out;

    float *qp, *kp, *vp, *xp;
    cudaGetSymbolAddress((void**)&qp, g_q);
    cudaGetSymbolAddress((void**)&kp, g_k);
    cudaGetSymbolAddress((void**)&vp, g_v);
    cudaGetSymbolAddress((void**)&xp, g_x);

    cudaFuncSetAttribute(attn_topk_kernel,
                         cudaFuncAttributeMaxDynamicSharedMemorySize, ATTN_SMEM);

    const dim3 gblk(8, 32);
    gemm_exact_kernel<<<gblk, 256>>>(hs, Wq, bq, qp, 1.0f);     // exact fp32 order
    gemm_exact_kernel<<<gblk, 256>>>(hs, Wk, bk, kp, 0.125f);   // exact; *2^-3 exact
    gemm_tf32_kernel<0><<<gblk, 256>>>(hs, Wv, bv, vp, 1.0f);
    attn_topk_kernel<<<dim3(16, 32), 256, ATTN_SMEM>>>(qp, kp, vp, xp);
    gemm_tf32_kernel<1><<<gblk, 256>>>(xp, Wo, bo, out, 1.0f);
}

// round 17
// speedup vs baseline: 1.2475x; 1.0615x over previous
#include <cuda_runtime.h>
#include <math.h>

#define FULL 0xFFFFFFFFu

// Problem constants: B=2, N=2048, C=1024, H=16, D=64, TOPK=32
__device__ float g_q[2*16*2048*64];   // [B,H,N,D]  (exact-order fp32)
__device__ float g_k[2*16*2048*64];   // pre-scaled by 1/8 (exact: *2^-3)
__device__ float g_v[2*16*2048*64];
__device__ float g_x[2*2048*1024];    // attention output, [B,N,C]

__device__ __forceinline__ unsigned f2tf(float x) {
    unsigned r;
    asm("cvt.rna.tf32.f32 %0, %1;" : "=r"(r) : "f"(x));
    return r;
}
__device__ __forceinline__ void split2(float x, unsigned& h, unsigned& l) {
    h = f2tf(x);
    l = f2tf(x - __uint_as_float(h));
}
__device__ __forceinline__ void mma_tf32(float c[4], const unsigned a[4], const unsigned b[2]) {
    asm volatile(
        "mma.sync.aligned.m16n8k8.row.col.f32.tf32.tf32.f32 "
        "{%0,%1,%2,%3}, {%4,%5,%6,%7}, {%8,%9}, {%0,%1,%2,%3};\n"
        : "+f"(c[0]), "+f"(c[1]), "+f"(c[2]), "+f"(c[3])
        : "r"(a[0]), "r"(a[1]), "r"(a[2]), "r"(a[3]),
          "r"(b[0]), "r"(b[1]));
}
// zero-register global->shared 16B async copy (LDGSTS)
__device__ __forceinline__ void cp_async16(unsigned dst, const void* src) {
    asm volatile("cp.async.cg.shared.global [%0], [%1], 16;" :: "r"(dst), "l"(src));
}
__device__ __forceinline__ void cp_async_commit() {
    asm volatile("cp.async.commit_group;");
}
__device__ __forceinline__ void cp_async_wait0() {
    asm volatile("cp.async.wait_group 0;" ::: "memory");
}

// ---------------------------------------------------------------------------
// EXACT-ORDER fp32 SGEMM body (bit-matches standard SIMT sgemm): each output
// is one strictly k-ascending FMA chain. Double-buffered smem (from dynamic
// pool), register prefetch, one barrier per k-tile. Scatter to [B,H,N,D].
// ---------------------------------------------------------------------------
__device__ __forceinline__
void gemm_exact_body(const float* __restrict__ A, const float* __restrict__ W,
                     const float* __restrict__ bias, float* __restrict__ out,
                     float scale, float* dyn)
{
    // sA[2][8][132], sB[2][8][132]
    float (*sA)[8][132] = (float(*)[8][132])dyn;
    float (*sB)[8][132] = (float(*)[8][132])(dyn + 2 * 8 * 132);

    const int t  = threadIdx.x;
    const int tx = t & 15;
    const int ty = t >> 4;
    const int bm = blockIdx.y * 128;
    const int bn = blockIdx.x * 128;

    float c[8][8];
#pragma unroll
    for (int i = 0; i < 8; i++)
#pragma unroll
        for (int j = 0; j < 8; j++) c[i][j] = 0.f;

    const int lrow = t >> 1;              // 0..127
    const int lk   = (t & 1) * 4;         // 0 or 4
    const float* Ag = A + (size_t)(bm + lrow) * 1024 + lk;
    const float* Wg = W + (size_t)(bn + lrow) * 1024 + lk;

    {
        float4 av = *(const float4*)(Ag);
        float4 wv = *(const float4*)(Wg);
        sA[0][lk + 0][lrow] = av.x; sA[0][lk + 1][lrow] = av.y;
        sA[0][lk + 2][lrow] = av.z; sA[0][lk + 3][lrow] = av.w;
        sB[0][lk + 0][lrow] = wv.x; sB[0][lk + 1][lrow] = wv.y;
        sB[0][lk + 2][lrow] = wv.z; sB[0][lk + 3][lrow] = wv.w;
    }
    __syncthreads();

    for (int kt = 0; kt < 128; kt++) {
        const int cb = kt & 1;
        float4 av = make_float4(0.f, 0.f, 0.f, 0.f);
        float4 wv = make_float4(0.f, 0.f, 0.f, 0.f);
        if (kt < 127) {                        // prefetch next tile
            av = *(const float4*)(Ag + (kt + 1) * 8);
            wv = *(const float4*)(Wg + (kt + 1) * 8);
        }

#pragma unroll
        for (int kk = 0; kk < 8; kk++) {       // strictly ascending k
            float a[8], b[8];
            *(float4*)(a)     = *(const float4*)&sA[cb][kk][ty * 8];
            *(float4*)(a + 4) = *(const float4*)&sA[cb][kk][ty * 8 + 4];
            *(float4*)(b)     = *(const float4*)&sB[cb][kk][tx * 8];
            *(float4*)(b + 4) = *(const float4*)&sB[cb][kk][tx * 8 + 4];
#pragma unroll
            for (int i = 0; i < 8; i++)
#pragma unroll
                for (int j = 0; j < 8; j++)
                    c[i][j] = fmaf(a[i], b[j], c[i][j]);
        }

        if (kt < 127) {
            const int nb = cb ^ 1;
            sA[nb][lk + 0][lrow] = av.x; sA[nb][lk + 1][lrow] = av.y;
            sA[nb][lk + 2][lrow] = av.z; sA[nb][lk + 3][lrow] = av.w;
            sB[nb][lk + 0][lrow] = wv.x; sB[nb][lk + 1][lrow] = wv.y;
            sB[nb][lk + 2][lrow] = wv.z; sB[nb][lk + 3][lrow] = wv.w;
        }
        __syncthreads();                       // single barrier per tile
    }

#pragma unroll
    for (int i = 0; i < 8; i++)
#pragma unroll
        for (int j = 0; j < 8; j++) {
            const int mg = bm + ty * 8 + i;
            const int ng = bn + tx * 8 + j;
            const float val = (c[i][j] + bias[ng]) * scale;
            const int b = mg >> 11, ns = mg & 2047;
            const int h = ng >> 6,  d  = ng & 63;
            out[(size_t)((b * 16 + h) * 2048 + ns) * 64 + d] = val;
        }
}

// ---------------------------------------------------------------------------
// 2-way-split 3-mma tf32 GEMM body (~1e-7 values) — value-only paths.
// MODE 0: scatter [B,H,N,D]; MODE 1: row-major. smem from dynamic pool.
// ---------------------------------------------------------------------------
template<int MODE>
__device__ __forceinline__
void gemm_tf32_body(const float* __restrict__ A, const float* __restrict__ W,
                    const float* __restrict__ bias, float* __restrict__ out,
                    float scale, unsigned* dyn)
{
    // 4 planes [128][20]: Ah, Al, Bh, Bl
    unsigned (*sAh)[20] = (unsigned(*)[20])dyn;
    unsigned (*sAl)[20] = (unsigned(*)[20])(dyn + 128 * 20);
    unsigned (*sBh)[20] = (unsigned(*)[20])(dyn + 2 * 128 * 20);
    unsigned (*sBl)[20] = (unsigned(*)[20])(dyn + 3 * 128 * 20);

    const int t    = threadIdx.x;
    const int lane = t & 31;
    const int w    = t >> 5;
    const int grp  = lane >> 2;
    const int tg   = lane & 3;
    const int wm   = w & 1;
    const int wn   = w >> 1;
    const int bm   = blockIdx.y * 128;
    const int bn   = blockIdx.x * 128;

    float c[4][4][4];
#pragma unroll
    for (int mt = 0; mt < 4; mt++)
#pragma unroll
        for (int nt = 0; nt < 4; nt++)
#pragma unroll
            for (int e = 0; e < 4; e++) c[mt][nt][e] = 0.f;

    const int lrow = t >> 1;
    const int lcol = (t & 1) * 8;
    const float* Ag = A + (size_t)(bm + lrow) * 1024 + lcol;
    const float* Wg = W + (size_t)(bn + lrow) * 1024 + lcol;

    for (int kt = 0; kt < 64; kt++) {
        float av[8], wv[8];
        *(float4*)(av)     = *(const float4*)(Ag + kt * 16);
        *(float4*)(av + 4) = *(const float4*)(Ag + kt * 16 + 4);
        *(float4*)(wv)     = *(const float4*)(Wg + kt * 16);
        *(float4*)(wv + 4) = *(const float4*)(Wg + kt * 16 + 4);
        __syncthreads();
#pragma unroll
        for (int j = 0; j < 8; j++) {
            unsigned h, l;
            split2(av[j], h, l);
            sAh[lrow][lcol + j] = h; sAl[lrow][lcol + j] = l;
            split2(wv[j], h, l);
            sBh[lrow][lcol + j] = h; sBl[lrow][lcol + j] = l;
        }
        __syncthreads();

#pragma unroll
        for (int ks = 0; ks < 2; ks++) {
            const int kk = ks * 8 + tg;
            unsigned ah[4][4], al[4][4], bh2[4][2], bl2[4][2];
#pragma unroll
            for (int mt = 0; mt < 4; mt++) {
                const int r = wm * 64 + mt * 16 + grp;
                ah[mt][0] = sAh[r][kk];     al[mt][0] = sAl[r][kk];
                ah[mt][1] = sAh[r + 8][kk]; al[mt][1] = sAl[r + 8][kk];
                ah[mt][2] = sAh[r][kk + 4]; al[mt][2] = sAl[r][kk + 4];
                ah[mt][3] = sAh[r + 8][kk + 4]; al[mt][3] = sAl[r + 8][kk + 4];
            }
#pragma unroll
            for (int nt = 0; nt < 4; nt++) {
                const int q = wn * 32 + nt * 8 + grp;
                bh2[nt][0] = sBh[q][kk];     bl2[nt][0] = sBl[q][kk];
                bh2[nt][1] = sBh[q][kk + 4]; bl2[nt][1] = sBl[q][kk + 4];
            }
#pragma unroll
            for (int mt = 0; mt < 4; mt++)
#pragma unroll
                for (int nt = 0; nt < 4; nt++) {
                    mma_tf32(c[mt][nt], ah[mt], bl2[nt]);
                    mma_tf32(c[mt][nt], al[mt], bh2[nt]);
                    mma_tf32(c[mt][nt], ah[mt], bh2[nt]);
                }
        }
    }

#pragma unroll
    for (int mt = 0; mt < 4; mt++)
#pragma unroll
        for (int nt = 0; nt < 4; nt++) {
            const int mg0 = bm + wm * 64 + mt * 16 + grp;
            const int ng0 = bn + wn * 32 + nt * 8 + tg * 2;
#pragma unroll
            for (int e = 0; e < 4; e++) {
                const int mg = mg0 + (e >> 1) * 8;
                const int ng = ng0 + (e & 1);
                const float val = (c[mt][nt][e] + bias[ng]) * scale;
                if (MODE == 0) {
                    const int b = mg >> 11, ns = mg & 2047;
                    const int h = ng >> 6,  d  = ng & 63;
                    out[(size_t)((b * 16 + h) * 2048 + ns) * 64 + d] = val;
                } else {
                    out[(size_t)mg * 1024 + ng] = val;
                }
            }
        }
}

// ---------------------------------------------------------------------------
// Fused QKV projection: ONE launch, grid (8, 32, 3). Per-block path select:
//   z=0: exact-order fp32 -> g_q (scale 1)        [selection-critical]
//   z=1: exact-order fp32 -> g_k (scale 2^-3)     [selection-critical]
//   z=2: tf32 split2      -> g_v (scale 1)        [value-only]
// 768 CTAs pack ~2.6 waves vs 3 gap-separated 86%-full waves.
// Dynamic smem: max(16896, 40960) = 40960 B.
// ---------------------------------------------------------------------------
#define QKV_SMEM 40960

__global__ __launch_bounds__(256, 2)
void qkv_kernel(const float* __restrict__ hs,
                const float* __restrict__ Wq, const float* __restrict__ bq,
                const float* __restrict__ Wk, const float* __restrict__ bk,
                const float* __restrict__ Wv, const float* __restrict__ bv,
                float* __restrict__ qp, float* __restrict__ kp,
                float* __restrict__ vp)
{
    extern __shared__ float dynf[];
    const int z = blockIdx.z;
    if (z == 0)      gemm_exact_body(hs, Wq, bq, qp, 1.0f,   dynf);
    else if (z == 1) gemm_exact_body(hs, Wk, bk, kp, 0.125f, dynf);
    else             gemm_tf32_body<0>(hs, Wv, bv, vp, 1.0f, (unsigned*)dynf);
}

// ---------------------------------------------------------------------------
// Out-projection: tf32 split2, row-major output (value-only path).
// ---------------------------------------------------------------------------
__global__ __launch_bounds__(256, 2)
void out_proj_kernel(const float* __restrict__ A, const float* __restrict__ W,
                     const float* __restrict__ bias, float* __restrict__ out)
{
    extern __shared__ float dynf[];
    gemm_tf32_body<1>(A, W, bias, out, 1.0f, (unsigned*)dynf);
}

// ---------------------------------------------------------------------------
// Fused attention (round-12 champion, byte-identical):
//  - scores: scalar fp32 FMA, strictly d-ascending chain (selection-critical)
//  - streaming top-32 (exact lax.top_k semantics, selection-critical)
//  - epilogue: order-free butterfly softmax + direct PV accumulation
// Double-buffered K tiles via cp.async, one barrier per tile, 2 CTAs/SM.
// CTA = 128 q-rows, 64-key tiles. grid (16, 32), 256 thr = 8 warps.
// smem: sQ[128][68] + 2*sK[64][68] + sS[128][68] = 104448 B.
// ---------------------------------------------------------------------------
#define ATTN_SMEM ((128 * 68 + 2 * 64 * 68 + 128 * 68) * 4)

__global__ __launch_bounds__(256, 2)
void attn_topk_kernel(const float* __restrict__ qb, const float* __restrict__ kb,
                      const float* __restrict__ vb, float* __restrict__ xb)
{
    extern __shared__ float smf[];
    float (*sQ)[68]  = (float(*)[68])smf;
    float (*sK0)[68] = (float(*)[68])(smf + 128 * 68);
    float (*sK1)[68] = (float(*)[68])(smf + 128 * 68 + 64 * 68);
    float (*sS)[68]  = (float(*)[68])(smf + 128 * 68 + 2 * 64 * 68);

    const int t    = threadIdx.x;
    const int lane = t & 31;
    const int w    = t >> 5;
    const int tx   = t & 15;
    const int ty   = t >> 4;
    const int bh   = blockIdx.y;
    const int q0   = blockIdx.x * 128;
    const int b    = bh >> 4, h = bh & 15;

    const float* Q  = qb + (size_t)bh * 2048 * 64;
    const float* Kp = kb + (size_t)bh * 2048 * 64;
    const float* Vp = vb + (size_t)bh * 2048 * 64;

    const int krow = t >> 4;        // 0..15
    const int kc4  = t & 15;        // 0..15

    // load Q tile [128][64] and preload K tile 0
    {
#pragma unroll
        for (int i = 0; i < 8; i++) {
            const int fi  = t + 256 * i;
            const int row = fi >> 4, c4 = fi & 15;
            *(float4*)&sQ[row][c4 * 4] =
                *(const float4*)(Q + (size_t)(q0 + row) * 64 + c4 * 4);
        }
#pragma unroll
        for (int i = 0; i < 4; i++) {
            const int row = krow + 16 * i;
            *(float4*)&sK0[row][kc4 * 4] =
                *(const float4*)(Kp + (size_t)row * 64 + kc4 * 4);
        }
    }
    __syncthreads();

    // top-32 lists: warp w owns rows w*16..w*16+15; lane holds rank lane (ascending)
    float lv[16]; int li[16];
#pragma unroll
    for (int rr = 0; rr < 16; rr++) { lv[rr] = -INFINITY; li[rr] = 0; }

    for (int kt = 0; kt < 32; kt++) {
        float (*cur)[68] = (kt & 1) ? sK1 : sK0;
        float (*nxt)[68] = (kt & 1) ? sK0 : sK1;

        // zero-register async prefetch of next K tile (overlaps compute+topk)
        if (kt < 31) {
#pragma unroll
            for (int i = 0; i < 4; i++) {
                const int row = krow + 16 * i;
                cp_async16((unsigned)__cvta_generic_to_shared(&nxt[row][kc4 * 4]),
                           Kp + (size_t)((kt + 1) * 64 + row) * 64 + kc4 * 4);
            }
            cp_async_commit();
        }

        // scores: rows ty*8+i (8), keys tx+16*j (4); d-ascending FMA chain
        float c[8][4];
#pragma unroll
        for (int i = 0; i < 8; i++)
#pragma unroll
            for (int j = 0; j < 4; j++) c[i][j] = 0.f;
#pragma unroll
        for (int dg = 0; dg < 16; dg++) {
            float4 a4[8], b4[4];
#pragma unroll
            for (int i = 0; i < 8; i++) a4[i] = *(const float4*)&sQ[ty * 8 + i][dg * 4];
#pragma unroll
            for (int j = 0; j < 4; j++) b4[j] = *(const float4*)&cur[tx + 16 * j][dg * 4];
#pragma unroll
            for (int i = 0; i < 8; i++)
#pragma unroll
                for (int j = 0; j < 4; j++) {
                    c[i][j] = fmaf(a4[i].x, b4[j].x, c[i][j]);
                    c[i][j] = fmaf(a4[i].y, b4[j].y, c[i][j]);
                    c[i][j] = fmaf(a4[i].z, b4[j].z, c[i][j]);
                    c[i][j] = fmaf(a4[i].w, b4[j].w, c[i][j]);
                }
        }
        // sS rows ty*8+i are warp-local (warp w <=> rows 16w..16w+15)
#pragma unroll
        for (int i = 0; i < 8; i++)
#pragma unroll
            for (int j = 0; j < 4; j++)
                sS[ty * 8 + i][tx + 16 * j] = c[i][j];
        __syncwarp();

        // streaming top-32 merge (ascending candidate index; strict > keeps
        // the earlier index on ties, matching lax.top_k)
#pragma unroll
        for (int rr = 0; rr < 16; rr++) {
            const int r = w * 16 + rr;
#pragma unroll
            for (int j = 0; j < 2; j++) {
                const float cand = sS[r][j * 32 + lane];
                const int   ci   = kt * 64 + j * 32 + lane;
                float minv = __shfl_sync(FULL, lv[rr], 0);
                unsigned mk = __ballot_sync(FULL, cand > minv);
                while (mk) {
                    const int src = __ffs(mk) - 1;
                    mk &= mk - 1;
                    const float cv   = __shfl_sync(FULL, cand, src);
                    const int   cidx = __shfl_sync(FULL, ci, src);
                    if (cv > minv) {
                        const unsigned lt  = __ballot_sync(FULL, lv[rr] < cv);
                        const int      pos = __popc(lt);
                        const float nv = __shfl_down_sync(FULL, lv[rr], 1);
                        const int   ni = __shfl_down_sync(FULL, li[rr], 1);
                        if (lane < pos - 1)       { lv[rr] = nv; li[rr] = ni; }
                        else if (lane == pos - 1) { lv[rr] = cv; li[rr] = cidx; }
                        minv = __shfl_sync(FULL, lv[rr], 0);
                    }
                }
            }
        }

        if (kt < 31) cp_async_wait0();   // prefetched tile landed
        __syncthreads();                 // single barrier per tile
    }

    // FAST epilogue (value-only path; order-free): butterfly softmax sum,
    // direct PV accumulation in list order.
#pragma unroll 1
    for (int rr = 0; rr < 16; rr++) {
        const float v  = lv[rr];
        const int   ki = li[rr];
        const float mx = __shfl_sync(FULL, v, 31);   // lane 31 holds the max
        const float e  = expf(v - mx);
        float s = e;
#pragma unroll
        for (int o = 16; o > 0; o >>= 1) s += __shfl_xor_sync(FULL, s, o);
        const float wt = e / s;

        float acc0 = 0.f, acc1 = 0.f;
#pragma unroll
        for (int s2 = 0; s2 < 32; s2++) {
            const float w2 = __shfl_sync(FULL, wt, s2);
            const int   k2 = __shfl_sync(FULL, ki, s2);
            const float* vr = Vp + (size_t)k2 * 64;
            acc0 = fmaf(w2, vr[lane], acc0);
            acc1 = fmaf(w2, vr[lane + 32], acc1);
        }
        const int qrow = q0 + w * 16 + rr;
        float* xo = xb + (size_t)(b * 2048 + qrow) * 1024 + h * 64;
        xo[lane]      = acc0;
        xo[lane + 32] = acc1;
    }
}

// ---------------------------------------------------------------------------
extern "C" void kernel_launch(void* const* d_in, const int* in_sizes, int n_in,
                              void* d_out, int out_size)
{
    const float* hs = (const float*)d_in[0];
    const float* Wq = (const float*)d_in[1];
    const float* bq = (const float*)d_in[2];
    const float* Wk = (const float*)d_in[3];
    const float* bk = (const float*)d_in[4];
    const float* Wv = (const float*)d_in[5];
    const float* bv = (const float*)d_in[6];
    const float* Wo = (const float*)d_in[7];
    const float* bo = (const float*)d_in[8];
    float* out = (float*)d_out;

    float *qp, *kp, *vp, *xp;
    cudaGetSymbolAddress((void**)&qp, g_q);
    cudaGetSymbolAddress((void**)&kp, g_k);
    cudaGetSymbolAddress((void**)&vp, g_v);
    cudaGetSymbolAddress((void**)&xp, g_x);

    cudaFuncSetAttribute(attn_topk_kernel,
                         cudaFuncAttributeMaxDynamicSharedMemorySize, ATTN_SMEM);

    qkv_kernel<<<dim3(8, 32, 3), 256, QKV_SMEM>>>(hs, Wq, bq, Wk, bk, Wv, bv,
                                                  qp, kp, vp);
    attn_topk_kernel<<<dim3(16, 32), 256, ATTN_SMEM>>>(qp, kp, vp, xp);
    out_proj_kernel<<<dim3(8, 32), 256, QKV_SMEM>>>(xp, Wo, bo, out);
}